// round 11
// baseline (speedup 1.0000x reference)
#include <cuda_runtime.h>
#include <cuda_fp16.h>
#include <math.h>
#include <stdint.h>

// ---------------------------------------------------------------------------
// Problem constants
// ---------------------------------------------------------------------------
#define B_ 8
#define T_ 4096
#define D_ 512
#define M_TOTAL (B_ * T_)          // 32768
#define CHUNK 128
#define NCHUNK (T_ / CHUNK)        // 32
#define NSTH 8                     // k-stages (BK=64, fp16)

// ---------------------------------------------------------------------------
// Scratch
// ---------------------------------------------------------------------------
__device__ __half g_hbufA[(size_t)M_TOTAL * D_];   // cum-mean, fp16 interleaved
__device__ __half g_hbufB[(size_t)M_TOTAL * D_];   // H, fp16 interleaved
__device__ float  g_fbuf[(size_t)M_TOTAL * D_];    // pre-LN fp32
__device__ float  g_partial[B_ * NCHUNK * D_];
__device__ float  g_summ[B_ * D_];                 // summ_proj
__device__ float  g_summ2[B_ * D_];                // summ_proj@W_out + b_out
__device__ __half g_hWt[2 * (size_t)D_ * D_];      // [0]=W_hist^T il, [1]=Wc^T il

// ---------------------------------------------------------------------------
// Helpers
// ---------------------------------------------------------------------------
__device__ __forceinline__ uint32_t smem_u32(const void* p) {
    uint32_t a;
    asm("{ .reg .u64 t; cvta.to.shared.u64 t, %1; cvt.u32.u64 %0, t; }"
        : "=r"(a) : "l"(p));
    return a;
}
__device__ __forceinline__ void mma_f16_16x8x16(float* d, const uint32_t* a,
                                                const uint32_t* b) {
    asm volatile(
        "mma.sync.aligned.m16n8k16.row.col.f32.f16.f16.f32 "
        "{%0,%1,%2,%3}, {%4,%5,%6,%7}, {%8,%9}, {%0,%1,%2,%3};"
        : "+f"(d[0]), "+f"(d[1]), "+f"(d[2]), "+f"(d[3])
        : "r"(a[0]), "r"(a[1]), "r"(a[2]), "r"(a[3]),
          "r"(b[0]), "r"(b[1]));
}

#define CP_ASYNC16(dst, src) \
    asm volatile("cp.async.cg.shared.global [%0], [%1], 16;" \
                 :: "r"(dst), "l"(src) : "memory")
#define CP_COMMIT() asm volatile("cp.async.commit_group;" ::: "memory")
#define CP_WAIT1()  asm volatile("cp.async.wait_group 1;" ::: "memory")
#define CP_WAIT0()  asm volatile("cp.async.wait_group 0;" ::: "memory")

// fp16 k16-fragment interleave within a 64-wide k-stage
__device__ __forceinline__ int kpos64(int kk) {          // kk in [0,64)
    int g = kk >> 4, j = kk & 15;
    int lr = (j >> 1) & 3;
    int idx = ((j >> 3) << 1) | (j & 1);
    return (g >> 1) * 32 + lr * 8 + (g & 1) * 4 + idx;
}
__device__ __forceinline__ size_t ileave16(int m, int k) {   // offset in halves
    return ((size_t)((m >> 7) * NSTH + (k >> 6)) * 128 + (m & 127)) * 64
           + kpos64(k & 63);
}
__device__ __forceinline__ int swz8(int r) {
    return (((r & 1) << 2) | ((r >> 1) & 3));
}

// ---------------------------------------------------------------------------
// chunk_sum (launch 0)
// ---------------------------------------------------------------------------
__global__ void chunk_sum_kernel(const float* __restrict__ dec) {
    int bc = blockIdx.x;
    int b = bc / NCHUNK, c = bc % NCHUNK;
    int d = threadIdx.x;
    const float* p = dec + ((size_t)(b * T_ + c * CHUNK)) * D_ + d;
    float s = 0.f;
    #pragma unroll 8
    for (int t = 0; t < CHUNK; ++t) s += p[(size_t)t * D_];
    g_partial[(size_t)bc * D_ + d] = s;
}

// ---------------------------------------------------------------------------
// prep_kernel (launch 1): prefix + W_hist transpose + Wc = W2@W_out (fp32)
//                         + summ_proj.  360 blocks x 512 threads.
// ---------------------------------------------------------------------------
__global__ __launch_bounds__(512)
void prep_kernel(const float* __restrict__ summ, const float* __restrict__ W1,
                 const float* __restrict__ W_hist, const float* __restrict__ W2,
                 const float* __restrict__ W_out) {
    __shared__ float sh[8448];             // 33 KB (As 64x68 + Bs 64x64)
    int blk = blockIdx.x;
    int tid = threadIdx.x;

    if (blk < 8) {                         // ---- chunk exclusive prefix ----
        int b = blk, d = tid;
        float run = 0.f;
        for (int c = 0; c < NCHUNK; ++c) {
            size_t idx = ((size_t)(b * NCHUNK + c)) * D_ + d;
            float v = g_partial[idx];
            g_partial[idx] = run;
            run += v;
        }
    } else if (blk < 264) {                // ---- W_hist transpose+interleave ----
        int r = blk - 8;                   // 16x16 tile grid
        int bx = (r & 15) * 32, by = (r >> 4) * 32;
        if (tid < 256) {
            int x = tid & 31, y = tid >> 5;
            float(*t)[33] = (float(*)[33])sh;
            #pragma unroll
            for (int i = 0; i < 32; i += 8)
                t[y + i][x] = W_hist[(size_t)(by + y + i) * D_ + bx + x];
            __syncthreads();
            #pragma unroll
            for (int i = 0; i < 32; i += 8)
                g_hWt[ileave16(bx + y + i, by + x)] = __float2half_rn(t[x][y + i]);
        } else {
            __syncthreads();
        }
    } else if (blk < 328) {                // ---- Wc = W2 @ W_out (64x64 tile) ----
        int widx = blk - 264;              // 0..63
        int i0 = (widx & 7) * 64;          // rows of Wc (k of gemm2 B operand)
        int j0 = (widx >> 3) * 64;         // cols of Wc (n)
        float* As = sh;                    // [64][68]  (68 floats = 272B, 16B-aligned rows)
        float* Bs = sh + 64 * 68;          // [64][64]
        int r = tid >> 3;                  // 0..63
        int c8 = (tid & 7) * 8;
        int ti = tid >> 3;                 // output row
        int tjg = tid & 7;                 // output col group (8 cols)
        float a8[8];
        #pragma unroll
        for (int j = 0; j < 8; ++j) a8[j] = 0.f;

        for (int k0 = 0; k0 < 512; k0 += 64) {
            __syncthreads();
            *(float4*)&As[r * 68 + c8]     = *(const float4*)&W2[(size_t)(i0 + r) * D_ + k0 + c8];
            *(float4*)&As[r * 68 + c8 + 4] = *(const float4*)&W2[(size_t)(i0 + r) * D_ + k0 + c8 + 4];
            *(float4*)&Bs[r * 64 + c8]     = *(const float4*)&W_out[(size_t)(k0 + r) * D_ + j0 + c8];
            *(float4*)&Bs[r * 64 + c8 + 4] = *(const float4*)&W_out[(size_t)(k0 + r) * D_ + j0 + c8 + 4];
            __syncthreads();
            #pragma unroll 8
            for (int kk = 0; kk < 64; ++kk) {
                float a = As[ti * 68 + kk];
                const float* bp = &Bs[kk * 64 + tjg * 8];
                float4 b0 = *(const float4*)bp;
                float4 b1 = *(const float4*)(bp + 4);
                a8[0] = fmaf(a, b0.x, a8[0]); a8[1] = fmaf(a, b0.y, a8[1]);
                a8[2] = fmaf(a, b0.z, a8[2]); a8[3] = fmaf(a, b0.w, a8[3]);
                a8[4] = fmaf(a, b1.x, a8[4]); a8[5] = fmaf(a, b1.y, a8[5]);
                a8[6] = fmaf(a, b1.z, a8[6]); a8[7] = fmaf(a, b1.w, a8[7]);
            }
        }
        // store transposed+interleaved: Bt(n=j, k=i) = Wc[i][j]
        __half* Wc = g_hWt + (size_t)D_ * D_;
        int ii = i0 + ti;
        int kp = kpos64(ii & 63);
        int khi = ii >> 6;
        #pragma unroll
        for (int j = 0; j < 8; ++j) {
            int jj = j0 + tjg * 8 + j;
            size_t off = ((size_t)((jj >> 7) * NSTH + khi)) * 8192
                         + (size_t)(jj & 127) * 64 + kp;
            Wc[off] = __float2half_rn(a8[j]);
        }
    } else {                               // ---- summ_proj (fp32) ----
        int sidx = blk - 328;
        int b = sidx >> 2;
        int n0 = (sidx & 3) * 128;
        float* s = sh;
        float* red = sh + 512;
        int nl = tid & 127;
        int kg = tid >> 7;
        for (int i = tid; i < D_; i += 512) s[i] = summ[b * D_ + i];
        __syncthreads();
        float acc = 0.f;
        int k0 = kg * 128;
        #pragma unroll 8
        for (int k = 0; k < 128; ++k)
            acc = fmaf(s[k0 + k], W1[(size_t)(k0 + k) * D_ + n0 + nl], acc);
        red[kg * 128 + nl] = acc;
        __syncthreads();
        if (kg == 0)
            g_summ[b * D_ + n0 + nl] =
                red[nl] + red[128 + nl] + red[256 + nl] + red[384 + nl];
    }
}

// ---------------------------------------------------------------------------
// sp2_kernel: g_summ2 = summ_proj @ W_out + b_out   (32 blocks)
// ---------------------------------------------------------------------------
__global__ __launch_bounds__(512)
void sp2_kernel(const float* __restrict__ W_out, const float* __restrict__ b_out) {
    __shared__ float s[512];
    __shared__ float red[512];
    int b = blockIdx.x >> 2;
    int n0 = (blockIdx.x & 3) * 128;
    int tid = threadIdx.x;
    int nl = tid & 127;
    int kg = tid >> 7;
    for (int i = tid; i < D_; i += 512) s[i] = g_summ[b * D_ + i];
    __syncthreads();
    float acc = 0.f;
    int k0 = kg * 128;
    #pragma unroll 8
    for (int k = 0; k < 128; ++k)
        acc = fmaf(s[k0 + k], W_out[(size_t)(k0 + k) * D_ + n0 + nl], acc);
    red[kg * 128 + nl] = acc;
    __syncthreads();
    if (kg == 0)
        g_summ2[b * D_ + n0 + nl] = b_out[n0 + nl] +
            red[nl] + red[128 + nl] + red[256 + nl] + red[384 + nl];
}

// ---------------------------------------------------------------------------
// cum_mean (launch 2) -> g_hbufA (fp16, interleaved), 4x unrolled
// ---------------------------------------------------------------------------
__global__ void cum_mean_kernel(const float* __restrict__ dec) {
    int bc = blockIdx.x;
    int b = bc / NCHUNK, c = bc % NCHUNK;
    int d = threadIdx.x;
    size_t base = ((size_t)(b * T_ + c * CHUNK)) * D_ + d;
    float run = g_partial[(size_t)bc * D_ + d];
    size_t obase = ((size_t)((b * NCHUNK + c) * NSTH + (d >> 6)) * 128) * 64
                   + kpos64(d & 63);
    for (int t = 0; t < CHUNK; t += 4) {
        float v0 = dec[base + (size_t)(t + 0) * D_];
        float v1 = dec[base + (size_t)(t + 1) * D_];
        float v2 = dec[base + (size_t)(t + 2) * D_];
        float v3 = dec[base + (size_t)(t + 3) * D_];
        int tt = c * CHUNK + t;
        run += v0;
        g_hbufA[obase + (size_t)(t + 0) * 64] = __float2half_rn(run / (float)(tt + 1));
        run += v1;
        g_hbufA[obase + (size_t)(t + 1) * 64] = __float2half_rn(run / (float)(tt + 2));
        run += v2;
        g_hbufA[obase + (size_t)(t + 2) * 64] = __float2half_rn(run / (float)(tt + 3));
        run += v3;
        g_hbufA[obase + (size_t)(t + 3) * 64] = __float2half_rn(run / (float)(tt + 4));
    }
}

// ---------------------------------------------------------------------------
// tc_gemm: mma.sync fp16 (m16n8k16), fully-unrolled 3-stage cp.async ring.
// Tile 128x128, BK=64, 8 warps, warp 32x64.
//   MODE 0: C(il,half) = half(tanh(acc + bias[col]))                (H)
//   MODE 2: C(fp32)    = tanh(vecb[b][col] - acc) + resid[row][col] (pre-LN x)
// ---------------------------------------------------------------------------
#define GM_THREADS 256
#define TILE_M 128
#define TILE_N 128
#define STG 16384                          // 128 rows x 128B

#define SM_A   0
#define SM_B   (3 * STG)                   // 49152
#define GEMM_SMEM (SM_B + 3 * STG)         // 98304 = 96KB -> 2 CTAs/SM

template <int MODE>
__global__ __launch_bounds__(GM_THREADS, 2)
void tc_gemm(const __half* __restrict__ A, const __half* __restrict__ Bt,
             const float* __restrict__ vec, const float* __restrict__ resid,
             void* __restrict__ Cv) {
    extern __shared__ char smem[];
    const uint32_t sbase = smem_u32(smem);

    const int tid = threadIdx.x;
    const int wid = tid >> 5, lane = tid & 31;
    const int row0 = blockIdx.y * TILE_M;
    const int col0 = blockIdx.x * TILE_N;
    const int wm = (wid & 3) * 32;
    const int wn = (wid >> 2) * 64;
    const int lq = lane >> 2;              // 0..7
    const int lr = lane & 3;               // 0..3

    const char* Ab = (const char*)A + (size_t)blockIdx.y * NSTH * 16384;
    const char* Bb = (const char*)Bt + (size_t)blockIdx.x * NSTH * 16384;
    const int frow = tid >> 3;             // 0..31
    const int fq = tid & 7;
    const uint32_t stchunk = (uint32_t)((fq ^ swz8(frow)) << 4);
    const uint32_t dA0 = sbase + SM_A + frow * 128 + stchunk;
    const uint32_t dB0 = sbase + SM_B + frow * 128 + stchunk;
    const size_t gsrc = (size_t)frow * 128 + fq * 16;

    const int swzl = swz8(lq);
    const int cc0 = (lr ^ swzl) << 4;
    const int cc1 = ((4 + lr) ^ swzl) << 4;

    const int aoff = (wm + lq) * 128;
    const int boff = (wn + lq) * 128;

    float acc[2][8][4];
    #pragma unroll
    for (int mt = 0; mt < 2; ++mt)
        #pragma unroll
        for (int nt = 0; nt < 8; ++nt)
            #pragma unroll
            for (int j = 0; j < 4; ++j) acc[mt][nt][j] = 0.f;

    #pragma unroll
    for (int p = 0; p < 2; ++p) {
        const char* as = Ab + (size_t)p * 16384;
        const char* bs = Bb + (size_t)p * 16384;
        #pragma unroll
        for (int i = 0; i < 4; ++i) {
            CP_ASYNC16(dA0 + p * STG + i * 4096, as + gsrc + (size_t)i * 4096);
            CP_ASYNC16(dB0 + p * STG + i * 4096, bs + gsrc + (size_t)i * 4096);
        }
        CP_COMMIT();
    }

    #pragma unroll
    for (int s = 0; s < NSTH; ++s) {
        const int buf = s % 3;
        if (s == NSTH - 1) { CP_WAIT0(); } else { CP_WAIT1(); }
        __syncthreads();
        if (s + 2 < NSTH) {
            const int bufn = (s + 2) % 3;
            const char* as = Ab + (size_t)(s + 2) * 16384;
            const char* bs = Bb + (size_t)(s + 2) * 16384;
            #pragma unroll
            for (int i = 0; i < 4; ++i) {
                CP_ASYNC16(dA0 + bufn * STG + i * 4096, as + gsrc + (size_t)i * 4096);
                CP_ASYNC16(dB0 + bufn * STG + i * 4096, bs + gsrc + (size_t)i * 4096);
            }
            CP_COMMIT();
        }

        const char* sa = smem + SM_A + buf * STG + aoff;
        const char* sb = smem + SM_B + buf * STG + boff;

        #pragma unroll
        for (int c = 0; c < 2; ++c) {
            const int co = c ? cc1 : cc0;
            uint4 qa0[2], qa1[2];
            #pragma unroll
            for (int mt = 0; mt < 2; ++mt) {
                qa0[mt] = *(const uint4*)(sa + mt * 2048 + co);
                qa1[mt] = *(const uint4*)(sa + mt * 2048 + 1024 + co);
            }
            uint32_t ag0[2][4], ag1[2][4];
            #pragma unroll
            for (int mt = 0; mt < 2; ++mt) {
                ag0[mt][0] = qa0[mt].x; ag0[mt][1] = qa1[mt].x;
                ag0[mt][2] = qa0[mt].y; ag0[mt][3] = qa1[mt].y;
                ag1[mt][0] = qa0[mt].z; ag1[mt][1] = qa1[mt].z;
                ag1[mt][2] = qa0[mt].w; ag1[mt][3] = qa1[mt].w;
            }
            uint4 pb = *(const uint4*)(sb + co);
            #pragma unroll
            for (int nt = 0; nt < 8; ++nt) {
                uint4 pc = pb;
                if (nt < 7)
                    pb = *(const uint4*)(sb + (nt + 1) * 1024 + co);
                uint32_t bg0[2] = { pc.x, pc.y };
                uint32_t bg1[2] = { pc.z, pc.w };
                mma_f16_16x8x16(acc[0][nt], ag0[0], bg0);
                mma_f16_16x8x16(acc[1][nt], ag0[1], bg0);
                mma_f16_16x8x16(acc[0][nt], ag1[0], bg1);
                mma_f16_16x8x16(acc[1][nt], ag1[1], bg1);
            }
        }
    }

    // ---------------- Epilogue ----------------
    const float* vbase = (MODE == 2) ? (vec + (size_t)(row0 / T_) * D_ + col0)
                                     : (vec + col0);
    if (MODE == 2) {
        float* C = (float*)Cv;
        #pragma unroll
        for (int mt = 0; mt < 2; ++mt) {
            int row = row0 + wm + mt * 16 + lq;
            #pragma unroll
            for (int nt = 0; nt < 8; ++nt) {
                int col = wn + nt * 8 + lr * 2;
                float b0 = vbase[col], b1 = vbase[col + 1];
                float c0 = acc[mt][nt][0], c1 = acc[mt][nt][1];
                float c2 = acc[mt][nt][2], c3 = acc[mt][nt][3];
                const float* r0p = resid + (size_t)row * D_ + col0 + col;
                const float* r1p = resid + (size_t)(row + 8) * D_ + col0 + col;
                float2 o0, o1;
                o0.x = tanhf(b0 - c0) + r0p[0];
                o0.y = tanhf(b1 - c1) + r0p[1];
                o1.x = tanhf(b0 - c2) + r1p[0];
                o1.y = tanhf(b1 - c3) + r1p[1];
                *(float2*)(C + (size_t)row * D_ + col0 + col) = o0;
                *(float2*)(C + (size_t)(row + 8) * D_ + col0 + col) = o1;
            }
        }
    } else {
        __half2* C2 = (__half2*)Cv;
        const size_t tilebase = (size_t)blockIdx.y * NSTH * 8192;   // halves
        #pragma unroll
        for (int mt = 0; mt < 2; ++mt) {
            int r = wm + mt * 16 + lq;
            #pragma unroll
            for (int nt = 0; nt < 8; ++nt) {
                int col = wn + nt * 8 + lr * 2;
                int k = col0 + col;
                size_t offh = tilebase + (size_t)(k >> 6) * 8192
                              + (size_t)r * 64 + kpos64(k & 63);
                float b0 = vbase[col], b1 = vbase[col + 1];
                float v0 = tanhf(acc[mt][nt][0] + b0);
                float v1 = tanhf(acc[mt][nt][1] + b1);
                float v2 = tanhf(acc[mt][nt][2] + b0);
                float v3 = tanhf(acc[mt][nt][3] + b1);
                C2[offh >> 1]         = __floats2half2_rn(v0, v1);   // (r,   k:k+1)
                C2[(offh >> 1) + 256] = __floats2half2_rn(v2, v3);   // (r+8, k:k+1)
            }
        }
    }
}

// ---------------------------------------------------------------------------
// LayerNorm (last launch)
// ---------------------------------------------------------------------------
__global__ __launch_bounds__(256)
void layernorm_kernel(const float* __restrict__ X,
                      const float* __restrict__ gamma,
                      const float* __restrict__ beta,
                      float* __restrict__ out) {
    int row = blockIdx.x;
    const float* x = X + (size_t)row * D_;
    int tid = threadIdx.x;

    float v0 = x[tid];
    float v1 = x[tid + 256];
    float s = v0 + v1;
    float sq = v0 * v0 + v1 * v1;

    __shared__ float redS[8], redQ[8];
    #pragma unroll
    for (int o = 16; o > 0; o >>= 1) {
        s  += __shfl_down_sync(0xffffffffu, s, o);
        sq += __shfl_down_sync(0xffffffffu, sq, o);
    }
    if ((tid & 31) == 0) { redS[tid >> 5] = s; redQ[tid >> 5] = sq; }
    __syncthreads();
    if (tid < 32) {
        float a = (tid < 8) ? redS[tid] : 0.f;
        float b = (tid < 8) ? redQ[tid] : 0.f;
        #pragma unroll
        for (int o = 4; o > 0; o >>= 1) {
            a += __shfl_down_sync(0xffffffffu, a, o);
            b += __shfl_down_sync(0xffffffffu, b, o);
        }
        if (tid == 0) { redS[0] = a; redQ[0] = b; }
    }
    __syncthreads();

    float mu = redS[0] * (1.0f / D_);
    float var = redQ[0] * (1.0f / D_) - mu * mu;
    float rstd = rsqrtf(var + 1e-6f);

    float* o = out + (size_t)row * D_;
    o[tid]       = (v0 - mu) * rstd * gamma[tid] + beta[tid];
    o[tid + 256] = (v1 - mu) * rstd * gamma[tid + 256] + beta[tid + 256];
}

// ---------------------------------------------------------------------------
// Launcher — launch index 3 = gemm0 (the ncu-profiled slot)
// ---------------------------------------------------------------------------
extern "C" void kernel_launch(void* const* d_in, const int* in_sizes, int n_in,
                              void* d_out, int out_size) {
    const float* summ   = (const float*)d_in[0];
    const float* dec    = (const float*)d_in[1];
    const float* W_hist = (const float*)d_in[2];
    const float* b_hist = (const float*)d_in[3];
    const float* W1     = (const float*)d_in[4];
    const float* W2     = (const float*)d_in[5];
    const float* W_out  = (const float*)d_in[6];
    const float* b_out  = (const float*)d_in[7];
    const float* gamma  = (const float*)d_in[8];
    const float* beta   = (const float*)d_in[9];
    float* out = (float*)d_out;

    __half *hbufA, *hbufB, *hwt;
    float *fbuf, *summ2;
    cudaGetSymbolAddress((void**)&hbufA, g_hbufA);
    cudaGetSymbolAddress((void**)&hbufB, g_hbufB);
    cudaGetSymbolAddress((void**)&fbuf,  g_fbuf);
    cudaGetSymbolAddress((void**)&summ2, g_summ2);
    cudaGetSymbolAddress((void**)&hwt,   g_hWt);
    __half* WtHist = hwt;
    __half* Wc     = hwt + (size_t)D_ * D_;

    cudaFuncSetAttribute(tc_gemm<0>, cudaFuncAttributeMaxDynamicSharedMemorySize, GEMM_SMEM);
    cudaFuncSetAttribute(tc_gemm<2>, cudaFuncAttributeMaxDynamicSharedMemorySize, GEMM_SMEM);

    // 0: chunk sums
    chunk_sum_kernel<<<B_ * NCHUNK, D_>>>(dec);
    // 1: prefix + W_hist transpose + Wc=W2@W_out + summ_proj (fused)
    prep_kernel<<<360, 512>>>(summ, W1, W_hist, W2, W_out);
    // 2: causal running mean -> hbufA (fp16, interleaved)
    cum_mean_kernel<<<B_ * NCHUNK, D_>>>(dec);

    dim3 ggrid(D_ / TILE_N, M_TOTAL / TILE_M);   // (4, 256)
    // 3: H = tanh(cum @ W_hist + b_hist)
    tc_gemm<0><<<ggrid, GM_THREADS, GEMM_SMEM>>>(hbufA, WtHist, b_hist, nullptr, hbufB);
    // 4: sp2 = summ_proj @ W_out + b_out (tiny)
    sp2_kernel<<<32, 512>>>(W_out, b_out);
    // 5: x = tanh(sp2[b] - H @ Wc) + dec
    tc_gemm<2><<<ggrid, GM_THREADS, GEMM_SMEM>>>(hbufB, Wc, summ2, dec, fbuf);

    // 6: LayerNorm
    layernorm_kernel<<<M_TOTAL, 256>>>(fbuf, gamma, beta, out);
}

// round 12
// speedup vs baseline: 1.0859x; 1.0859x over previous
#include <cuda_runtime.h>
#include <cuda_fp16.h>
#include <math.h>
#include <stdint.h>

// ---------------------------------------------------------------------------
// Problem constants
// ---------------------------------------------------------------------------
#define B_ 8
#define T_ 4096
#define D_ 512
#define M_TOTAL (B_ * T_)          // 32768
#define CHUNK 128
#define NCHUNK (T_ / CHUNK)        // 32
#define NSTH 8                     // k-stages (BK=64, fp16)

// ---------------------------------------------------------------------------
// Scratch
// ---------------------------------------------------------------------------
__device__ __half g_hbufA[(size_t)M_TOTAL * D_];   // cum-mean, fp16 interleaved
__device__ __half g_hbufB[(size_t)M_TOTAL * D_];   // H, fp16 interleaved
__device__ float  g_fbuf[(size_t)M_TOTAL * D_];    // pre-LN fp32
__device__ float  g_partial[B_ * NCHUNK * D_];
__device__ float  g_summ[B_ * D_];                 // summ_proj
__device__ float  g_summ2[B_ * D_];                // summ_proj@W_out + b_out
__device__ __half g_hWt[2 * (size_t)D_ * D_];      // [0]=W_hist^T il, [1]=Wc^T il

// ---------------------------------------------------------------------------
// Helpers
// ---------------------------------------------------------------------------
__device__ __forceinline__ uint32_t smem_u32(const void* p) {
    uint32_t a;
    asm("{ .reg .u64 t; cvta.to.shared.u64 t, %1; cvt.u32.u64 %0, t; }"
        : "=r"(a) : "l"(p));
    return a;
}
__device__ __forceinline__ void mma_f16_16x8x16(float* d, const uint32_t* a,
                                                const uint32_t* b) {
    asm volatile(
        "mma.sync.aligned.m16n8k16.row.col.f32.f16.f16.f32 "
        "{%0,%1,%2,%3}, {%4,%5,%6,%7}, {%8,%9}, {%0,%1,%2,%3};"
        : "+f"(d[0]), "+f"(d[1]), "+f"(d[2]), "+f"(d[3])
        : "r"(a[0]), "r"(a[1]), "r"(a[2]), "r"(a[3]),
          "r"(b[0]), "r"(b[1]));
}

#define CP_ASYNC16(dst, src) \
    asm volatile("cp.async.cg.shared.global [%0], [%1], 16;" \
                 :: "r"(dst), "l"(src) : "memory")
#define CP_COMMIT() asm volatile("cp.async.commit_group;" ::: "memory")
#define CP_WAIT1()  asm volatile("cp.async.wait_group 1;" ::: "memory")
#define CP_WAIT0()  asm volatile("cp.async.wait_group 0;" ::: "memory")

// fp16 k16-fragment interleave within a 64-wide k-stage
__device__ __forceinline__ int kpos64(int kk) {          // kk in [0,64)
    int g = kk >> 4, j = kk & 15;
    int lr = (j >> 1) & 3;
    int idx = ((j >> 3) << 1) | (j & 1);
    return (g >> 1) * 32 + lr * 8 + (g & 1) * 4 + idx;
}
__device__ __forceinline__ size_t ileave16(int m, int k) {   // offset in halves
    return ((size_t)((m >> 7) * NSTH + (k >> 6)) * 128 + (m & 127)) * 64
           + kpos64(k & 63);
}
__device__ __forceinline__ int swz8(int r) {
    return (((r & 1) << 2) | ((r >> 1) & 3));
}

// ---------------------------------------------------------------------------
// pre0_kernel (launch 0): chunk_sum (256) + Wc=W2@W_out (64) + summ_proj (32)
// 352 blocks x 512 threads. All branches dependency-free on other launches.
// ---------------------------------------------------------------------------
__global__ __launch_bounds__(512)
void pre0_kernel(const float* __restrict__ dec,
                 const float* __restrict__ summ, const float* __restrict__ W1,
                 const float* __restrict__ W2, const float* __restrict__ W_out) {
    __shared__ float sh[8448];             // 33 KB (Wc: As 64x68 + Bs 64x64)
    int blk = blockIdx.x;
    int tid = threadIdx.x;

    if (blk < 256) {                       // ---- chunk sums ----
        int b = blk / NCHUNK, c = blk % NCHUNK;
        const float* p = dec + ((size_t)(b * T_ + c * CHUNK)) * D_ + tid;
        float s = 0.f;
        #pragma unroll 8
        for (int t = 0; t < CHUNK; ++t) s += p[(size_t)t * D_];
        g_partial[(size_t)blk * D_ + tid] = s;
    } else if (blk < 320) {                // ---- Wc = W2 @ W_out (64x64 tile) ----
        int widx = blk - 256;              // 0..63
        int i0 = (widx & 7) * 64;          // rows of Wc (k of gemm2 B operand)
        int j0 = (widx >> 3) * 64;         // cols of Wc (n)
        float* As = sh;                    // [64][68] (272B rows, 16B-aligned)
        float* Bs = sh + 64 * 68;          // [64][64]
        int r = tid >> 3;                  // 0..63
        int c8 = (tid & 7) * 8;
        int ti = tid >> 3;                 // output row
        int tjg = tid & 7;                 // output col group (8 cols)
        float a8[8];
        #pragma unroll
        for (int j = 0; j < 8; ++j) a8[j] = 0.f;

        for (int k0 = 0; k0 < 512; k0 += 64) {
            __syncthreads();
            *(float4*)&As[r * 68 + c8]     = *(const float4*)&W2[(size_t)(i0 + r) * D_ + k0 + c8];
            *(float4*)&As[r * 68 + c8 + 4] = *(const float4*)&W2[(size_t)(i0 + r) * D_ + k0 + c8 + 4];
            *(float4*)&Bs[r * 64 + c8]     = *(const float4*)&W_out[(size_t)(k0 + r) * D_ + j0 + c8];
            *(float4*)&Bs[r * 64 + c8 + 4] = *(const float4*)&W_out[(size_t)(k0 + r) * D_ + j0 + c8 + 4];
            __syncthreads();
            #pragma unroll 8
            for (int kk = 0; kk < 64; ++kk) {
                float a = As[ti * 68 + kk];
                const float* bp = &Bs[kk * 64 + tjg * 8];
                float4 b0 = *(const float4*)bp;
                float4 b1 = *(const float4*)(bp + 4);
                a8[0] = fmaf(a, b0.x, a8[0]); a8[1] = fmaf(a, b0.y, a8[1]);
                a8[2] = fmaf(a, b0.z, a8[2]); a8[3] = fmaf(a, b0.w, a8[3]);
                a8[4] = fmaf(a, b1.x, a8[4]); a8[5] = fmaf(a, b1.y, a8[5]);
                a8[6] = fmaf(a, b1.z, a8[6]); a8[7] = fmaf(a, b1.w, a8[7]);
            }
        }
        // store transposed+interleaved: Bt(n=j, k=i) = Wc[i][j]
        __half* Wc = g_hWt + (size_t)D_ * D_;
        int ii = i0 + ti;
        int kp = kpos64(ii & 63);
        int khi = ii >> 6;
        #pragma unroll
        for (int j = 0; j < 8; ++j) {
            int jj = j0 + tjg * 8 + j;
            size_t off = ((size_t)((jj >> 7) * NSTH + khi)) * 8192
                         + (size_t)(jj & 127) * 64 + kp;
            Wc[off] = __float2half_rn(a8[j]);
        }
    } else {                               // ---- summ_proj (fp32) ----
        int sidx = blk - 320;
        int b = sidx >> 2;
        int n0 = (sidx & 3) * 128;
        float* s = sh;
        float* red = sh + 512;
        int nl = tid & 127;
        int kg = tid >> 7;
        for (int i = tid; i < D_; i += 512) s[i] = summ[b * D_ + i];
        __syncthreads();
        float acc = 0.f;
        int k0 = kg * 128;
        #pragma unroll 8
        for (int k = 0; k < 128; ++k)
            acc = fmaf(s[k0 + k], W1[(size_t)(k0 + k) * D_ + n0 + nl], acc);
        red[kg * 128 + nl] = acc;
        __syncthreads();
        if (kg == 0)
            g_summ[b * D_ + n0 + nl] =
                red[nl] + red[128 + nl] + red[256 + nl] + red[384 + nl];
    }
}

// ---------------------------------------------------------------------------
// prep_kernel (launch 1): prefix (8) + W_hist transpose (256) + sp2 (32)
// 296 blocks x 512 threads.
// ---------------------------------------------------------------------------
__global__ __launch_bounds__(512)
void prep_kernel(const float* __restrict__ W_hist,
                 const float* __restrict__ W_out, const float* __restrict__ b_out) {
    __shared__ float sh[1056];
    int blk = blockIdx.x;
    int tid = threadIdx.x;

    if (blk < 8) {                         // ---- chunk exclusive prefix ----
        int b = blk, d = tid;
        float run = 0.f;
        for (int c = 0; c < NCHUNK; ++c) {
            size_t idx = ((size_t)(b * NCHUNK + c)) * D_ + d;
            float v = g_partial[idx];
            g_partial[idx] = run;
            run += v;
        }
    } else if (blk < 264) {                // ---- W_hist transpose+interleave ----
        int r = blk - 8;                   // 16x16 tile grid
        int bx = (r & 15) * 32, by = (r >> 4) * 32;
        if (tid < 256) {
            int x = tid & 31, y = tid >> 5;
            float(*t)[33] = (float(*)[33])sh;
            #pragma unroll
            for (int i = 0; i < 32; i += 8)
                t[y + i][x] = W_hist[(size_t)(by + y + i) * D_ + bx + x];
            __syncthreads();
            #pragma unroll
            for (int i = 0; i < 32; i += 8)
                g_hWt[ileave16(bx + y + i, by + x)] = __float2half_rn(t[x][y + i]);
        } else {
            __syncthreads();
        }
    } else {                               // ---- sp2 = summ_proj@W_out + b_out ----
        int sidx = blk - 264;
        int b = sidx >> 2;
        int n0 = (sidx & 3) * 128;
        float* s = sh;
        float* red = sh + 512;
        int nl = tid & 127;
        int kg = tid >> 7;
        for (int i = tid; i < D_; i += 512) s[i] = g_summ[b * D_ + i];
        __syncthreads();
        float acc = 0.f;
        int k0 = kg * 128;
        #pragma unroll 8
        for (int k = 0; k < 128; ++k)
            acc = fmaf(s[k0 + k], W_out[(size_t)(k0 + k) * D_ + n0 + nl], acc);
        red[kg * 128 + nl] = acc;
        __syncthreads();
        if (kg == 0)
            g_summ2[b * D_ + n0 + nl] = b_out[n0 + nl] +
                red[nl] + red[128 + nl] + red[256 + nl] + red[384 + nl];
    }
}

// ---------------------------------------------------------------------------
// cum_mean (launch 2) -> g_hbufA (fp16, interleaved), 4x unrolled
// ---------------------------------------------------------------------------
__global__ void cum_mean_kernel(const float* __restrict__ dec) {
    int bc = blockIdx.x;
    int b = bc / NCHUNK, c = bc % NCHUNK;
    int d = threadIdx.x;
    size_t base = ((size_t)(b * T_ + c * CHUNK)) * D_ + d;
    float run = g_partial[(size_t)bc * D_ + d];
    size_t obase = ((size_t)((b * NCHUNK + c) * NSTH + (d >> 6)) * 128) * 64
                   + kpos64(d & 63);
    for (int t = 0; t < CHUNK; t += 4) {
        float v0 = dec[base + (size_t)(t + 0) * D_];
        float v1 = dec[base + (size_t)(t + 1) * D_];
        float v2 = dec[base + (size_t)(t + 2) * D_];
        float v3 = dec[base + (size_t)(t + 3) * D_];
        int tt = c * CHUNK + t;
        run += v0;
        g_hbufA[obase + (size_t)(t + 0) * 64] = __float2half_rn(run / (float)(tt + 1));
        run += v1;
        g_hbufA[obase + (size_t)(t + 1) * 64] = __float2half_rn(run / (float)(tt + 2));
        run += v2;
        g_hbufA[obase + (size_t)(t + 2) * 64] = __float2half_rn(run / (float)(tt + 3));
        run += v3;
        g_hbufA[obase + (size_t)(t + 3) * 64] = __float2half_rn(run / (float)(tt + 4));
    }
}

// ---------------------------------------------------------------------------
// tc_gemm: mma.sync fp16 (m16n8k16), fully-unrolled 3-stage cp.async ring.
// Tile 128x128, BK=64, 8 warps, warp 32x64.
//   MODE 0: C(il,half) = half(tanh(acc + bias[col]))                (H)
//   MODE 2: C(fp32)    = tanh(vecb[b][col] - acc) + resid[row][col] (pre-LN x)
// ---------------------------------------------------------------------------
#define GM_THREADS 256
#define TILE_M 128
#define TILE_N 128
#define STG 16384                          // 128 rows x 128B

#define SM_A   0
#define SM_B   (3 * STG)                   // 49152
#define GEMM_SMEM (SM_B + 3 * STG)         // 98304 = 96KB -> 2 CTAs/SM

template <int MODE>
__global__ __launch_bounds__(GM_THREADS, 2)
void tc_gemm(const __half* __restrict__ A, const __half* __restrict__ Bt,
             const float* __restrict__ vec, const float* __restrict__ resid,
             void* __restrict__ Cv) {
    extern __shared__ char smem[];
    const uint32_t sbase = smem_u32(smem);

    const int tid = threadIdx.x;
    const int wid = tid >> 5, lane = tid & 31;
    const int row0 = blockIdx.y * TILE_M;
    const int col0 = blockIdx.x * TILE_N;
    const int wm = (wid & 3) * 32;
    const int wn = (wid >> 2) * 64;
    const int lq = lane >> 2;              // 0..7
    const int lr = lane & 3;               // 0..3

    const char* Ab = (const char*)A + (size_t)blockIdx.y * NSTH * 16384;
    const char* Bb = (const char*)Bt + (size_t)blockIdx.x * NSTH * 16384;
    const int frow = tid >> 3;             // 0..31
    const int fq = tid & 7;
    const uint32_t stchunk = (uint32_t)((fq ^ swz8(frow)) << 4);
    const uint32_t dA0 = sbase + SM_A + frow * 128 + stchunk;
    const uint32_t dB0 = sbase + SM_B + frow * 128 + stchunk;
    const size_t gsrc = (size_t)frow * 128 + fq * 16;

    const int swzl = swz8(lq);
    const int cc0 = (lr ^ swzl) << 4;
    const int cc1 = ((4 + lr) ^ swzl) << 4;

    const int aoff = (wm + lq) * 128;
    const int boff = (wn + lq) * 128;

    float acc[2][8][4];
    #pragma unroll
    for (int mt = 0; mt < 2; ++mt)
        #pragma unroll
        for (int nt = 0; nt < 8; ++nt)
            #pragma unroll
            for (int j = 0; j < 4; ++j) acc[mt][nt][j] = 0.f;

    #pragma unroll
    for (int p = 0; p < 2; ++p) {
        const char* as = Ab + (size_t)p * 16384;
        const char* bs = Bb + (size_t)p * 16384;
        #pragma unroll
        for (int i = 0; i < 4; ++i) {
            CP_ASYNC16(dA0 + p * STG + i * 4096, as + gsrc + (size_t)i * 4096);
            CP_ASYNC16(dB0 + p * STG + i * 4096, bs + gsrc + (size_t)i * 4096);
        }
        CP_COMMIT();
    }

    #pragma unroll
    for (int s = 0; s < NSTH; ++s) {
        const int buf = s % 3;
        if (s == NSTH - 1) { CP_WAIT0(); } else { CP_WAIT1(); }
        __syncthreads();
        if (s + 2 < NSTH) {
            const int bufn = (s + 2) % 3;
            const char* as = Ab + (size_t)(s + 2) * 16384;
            const char* bs = Bb + (size_t)(s + 2) * 16384;
            #pragma unroll
            for (int i = 0; i < 4; ++i) {
                CP_ASYNC16(dA0 + bufn * STG + i * 4096, as + gsrc + (size_t)i * 4096);
                CP_ASYNC16(dB0 + bufn * STG + i * 4096, bs + gsrc + (size_t)i * 4096);
            }
            CP_COMMIT();
        }

        const char* sa = smem + SM_A + buf * STG + aoff;
        const char* sb = smem + SM_B + buf * STG + boff;

        #pragma unroll
        for (int c = 0; c < 2; ++c) {
            const int co = c ? cc1 : cc0;
            uint4 qa0[2], qa1[2];
            #pragma unroll
            for (int mt = 0; mt < 2; ++mt) {
                qa0[mt] = *(const uint4*)(sa + mt * 2048 + co);
                qa1[mt] = *(const uint4*)(sa + mt * 2048 + 1024 + co);
            }
            uint32_t ag0[2][4], ag1[2][4];
            #pragma unroll
            for (int mt = 0; mt < 2; ++mt) {
                ag0[mt][0] = qa0[mt].x; ag0[mt][1] = qa1[mt].x;
                ag0[mt][2] = qa0[mt].y; ag0[mt][3] = qa1[mt].y;
                ag1[mt][0] = qa0[mt].z; ag1[mt][1] = qa1[mt].z;
                ag1[mt][2] = qa0[mt].w; ag1[mt][3] = qa1[mt].w;
            }
            uint4 pb = *(const uint4*)(sb + co);
            #pragma unroll
            for (int nt = 0; nt < 8; ++nt) {
                uint4 pc = pb;
                if (nt < 7)
                    pb = *(const uint4*)(sb + (nt + 1) * 1024 + co);
                uint32_t bg0[2] = { pc.x, pc.y };
                uint32_t bg1[2] = { pc.z, pc.w };
                mma_f16_16x8x16(acc[0][nt], ag0[0], bg0);
                mma_f16_16x8x16(acc[1][nt], ag0[1], bg0);
                mma_f16_16x8x16(acc[0][nt], ag1[0], bg1);
                mma_f16_16x8x16(acc[1][nt], ag1[1], bg1);
            }
        }
    }

    // ---------------- Epilogue ----------------
    const float* vbase = (MODE == 2) ? (vec + (size_t)(row0 / T_) * D_ + col0)
                                     : (vec + col0);
    if (MODE == 2) {
        float* C = (float*)Cv;
        #pragma unroll
        for (int mt = 0; mt < 2; ++mt) {
            int row = row0 + wm + mt * 16 + lq;
            #pragma unroll
            for (int nt = 0; nt < 8; ++nt) {
                int col = wn + nt * 8 + lr * 2;
                float b0 = vbase[col], b1 = vbase[col + 1];
                float c0 = acc[mt][nt][0], c1 = acc[mt][nt][1];
                float c2 = acc[mt][nt][2], c3 = acc[mt][nt][3];
                const float* r0p = resid + (size_t)row * D_ + col0 + col;
                const float* r1p = resid + (size_t)(row + 8) * D_ + col0 + col;
                float2 o0, o1;
                o0.x = tanhf(b0 - c0) + r0p[0];
                o0.y = tanhf(b1 - c1) + r0p[1];
                o1.x = tanhf(b0 - c2) + r1p[0];
                o1.y = tanhf(b1 - c3) + r1p[1];
                *(float2*)(C + (size_t)row * D_ + col0 + col) = o0;
                *(float2*)(C + (size_t)(row + 8) * D_ + col0 + col) = o1;
            }
        }
    } else {
        __half2* C2 = (__half2*)Cv;
        const size_t tilebase = (size_t)blockIdx.y * NSTH * 8192;   // halves
        #pragma unroll
        for (int mt = 0; mt < 2; ++mt) {
            int r = wm + mt * 16 + lq;
            #pragma unroll
            for (int nt = 0; nt < 8; ++nt) {
                int col = wn + nt * 8 + lr * 2;
                int k = col0 + col;
                size_t offh = tilebase + (size_t)(k >> 6) * 8192
                              + (size_t)r * 64 + kpos64(k & 63);
                float b0 = vbase[col], b1 = vbase[col + 1];
                float v0 = tanhf(acc[mt][nt][0] + b0);
                float v1 = tanhf(acc[mt][nt][1] + b1);
                float v2 = tanhf(acc[mt][nt][2] + b0);
                float v3 = tanhf(acc[mt][nt][3] + b1);
                C2[offh >> 1]         = __floats2half2_rn(v0, v1);   // (r,   k:k+1)
                C2[(offh >> 1) + 256] = __floats2half2_rn(v2, v3);   // (r+8, k:k+1)
            }
        }
    }
}

// ---------------------------------------------------------------------------
// LayerNorm (last launch)
// ---------------------------------------------------------------------------
__global__ __launch_bounds__(256)
void layernorm_kernel(const float* __restrict__ X,
                      const float* __restrict__ gamma,
                      const float* __restrict__ beta,
                      float* __restrict__ out) {
    int row = blockIdx.x;
    const float* x = X + (size_t)row * D_;
    int tid = threadIdx.x;

    float v0 = x[tid];
    float v1 = x[tid + 256];
    float s = v0 + v1;
    float sq = v0 * v0 + v1 * v1;

    __shared__ float redS[8], redQ[8];
    #pragma unroll
    for (int o = 16; o > 0; o >>= 1) {
        s  += __shfl_down_sync(0xffffffffu, s, o);
        sq += __shfl_down_sync(0xffffffffu, sq, o);
    }
    if ((tid & 31) == 0) { redS[tid >> 5] = s; redQ[tid >> 5] = sq; }
    __syncthreads();
    if (tid < 32) {
        float a = (tid < 8) ? redS[tid] : 0.f;
        float b = (tid < 8) ? redQ[tid] : 0.f;
        #pragma unroll
        for (int o = 4; o > 0; o >>= 1) {
            a += __shfl_down_sync(0xffffffffu, a, o);
            b += __shfl_down_sync(0xffffffffu, b, o);
        }
        if (tid == 0) { redS[0] = a; redQ[0] = b; }
    }
    __syncthreads();

    float mu = redS[0] * (1.0f / D_);
    float var = redQ[0] * (1.0f / D_) - mu * mu;
    float rstd = rsqrtf(var + 1e-6f);

    float* o = out + (size_t)row * D_;
    o[tid]       = (v0 - mu) * rstd * gamma[tid] + beta[tid];
    o[tid + 256] = (v1 - mu) * rstd * gamma[tid + 256] + beta[tid + 256];
}

// ---------------------------------------------------------------------------
// Launcher — launch index 3 = gemm0 (the ncu-profiled slot)
// ---------------------------------------------------------------------------
extern "C" void kernel_launch(void* const* d_in, const int* in_sizes, int n_in,
                              void* d_out, int out_size) {
    const float* summ   = (const float*)d_in[0];
    const float* dec    = (const float*)d_in[1];
    const float* W_hist = (const float*)d_in[2];
    const float* b_hist = (const float*)d_in[3];
    const float* W1     = (const float*)d_in[4];
    const float* W2     = (const float*)d_in[5];
    const float* W_out  = (const float*)d_in[6];
    const float* b_out  = (const float*)d_in[7];
    const float* gamma  = (const float*)d_in[8];
    const float* beta   = (const float*)d_in[9];
    float* out = (float*)d_out;

    __half *hbufA, *hbufB, *hwt;
    float *fbuf, *summ2;
    cudaGetSymbolAddress((void**)&hbufA, g_hbufA);
    cudaGetSymbolAddress((void**)&hbufB, g_hbufB);
    cudaGetSymbolAddress((void**)&fbuf,  g_fbuf);
    cudaGetSymbolAddress((void**)&summ2, g_summ2);
    cudaGetSymbolAddress((void**)&hwt,   g_hWt);
    __half* WtHist = hwt;
    __half* Wc     = hwt + (size_t)D_ * D_;

    cudaFuncSetAttribute(tc_gemm<0>, cudaFuncAttributeMaxDynamicSharedMemorySize, GEMM_SMEM);
    cudaFuncSetAttribute(tc_gemm<2>, cudaFuncAttributeMaxDynamicSharedMemorySize, GEMM_SMEM);

    // 0: chunk sums + Wc=W2@W_out + summ_proj (all independent)
    pre0_kernel<<<352, 512>>>(dec, summ, W1, W2, W_out);
    // 1: prefix + W_hist transpose + sp2
    prep_kernel<<<296, 512>>>(W_hist, W_out, b_out);
    // 2: causal running mean -> hbufA (fp16, interleaved)
    cum_mean_kernel<<<B_ * NCHUNK, D_>>>(dec);

    dim3 ggrid(D_ / TILE_N, M_TOTAL / TILE_M);   // (4, 256)
    // 3: H = tanh(cum @ W_hist + b_hist)
    tc_gemm<0><<<ggrid, GM_THREADS, GEMM_SMEM>>>(hbufA, WtHist, b_hist, nullptr, hbufB);
    // 4: x = tanh(sp2[b] - H @ Wc) + dec
    tc_gemm<2><<<ggrid, GM_THREADS, GEMM_SMEM>>>(hbufB, Wc, summ2, dec, fbuf);

    // 5: LayerNorm
    layernorm_kernel<<<M_TOTAL, 256>>>(fbuf, gamma, beta, out);
}

// round 14
// speedup vs baseline: 1.3479x; 1.2413x over previous
#include <cuda_runtime.h>
#include <cuda_fp16.h>
#include <math.h>
#include <stdint.h>

// ---------------------------------------------------------------------------
// Problem constants
// ---------------------------------------------------------------------------
#define B_ 8
#define T_ 4096
#define D_ 512
#define M_TOTAL (B_ * T_)          // 32768
#define CHUNK 128
#define NCHUNK (T_ / CHUNK)        // 32
#define NSTH 8                     // k-stages (BK=64, fp16)

// ---------------------------------------------------------------------------
// Scratch
// ---------------------------------------------------------------------------
__device__ __half g_hbufA[(size_t)M_TOTAL * D_];   // cum-mean, fp16 interleaved
__device__ __half g_hbufB[(size_t)M_TOTAL * D_];   // H, fp16 interleaved
__device__ float  g_fbuf[(size_t)M_TOTAL * D_];    // pre-LN fp32
__device__ float  g_partial[B_ * NCHUNK * D_];
__device__ float  g_summ[B_ * D_];                 // summ_proj
__device__ float  g_summ2[B_ * D_];                // summ_proj@W_out + b_out
__device__ __half g_hWt[2 * (size_t)D_ * D_];      // [0]=W_hist^T il, [1]=Wc^T il

// ---------------------------------------------------------------------------
// Helpers
// ---------------------------------------------------------------------------
__device__ __forceinline__ uint32_t smem_u32(const void* p) {
    uint32_t a;
    asm("{ .reg .u64 t; cvta.to.shared.u64 t, %1; cvt.u32.u64 %0, t; }"
        : "=r"(a) : "l"(p));
    return a;
}
__device__ __forceinline__ void mma_f16_16x8x16(float* d, const uint32_t* a,
                                                const uint32_t* b) {
    asm volatile(
        "mma.sync.aligned.m16n8k16.row.col.f32.f16.f16.f32 "
        "{%0,%1,%2,%3}, {%4,%5,%6,%7}, {%8,%9}, {%0,%1,%2,%3};"
        : "+f"(d[0]), "+f"(d[1]), "+f"(d[2]), "+f"(d[3])
        : "r"(a[0]), "r"(a[1]), "r"(a[2]), "r"(a[3]),
          "r"(b[0]), "r"(b[1]));
}

#define CP_ASYNC16(dst, src) \
    asm volatile("cp.async.cg.shared.global [%0], [%1], 16;" \
                 :: "r"(dst), "l"(src) : "memory")
#define CP_COMMIT() asm volatile("cp.async.commit_group;" ::: "memory")
#define CP_WAIT1()  asm volatile("cp.async.wait_group 1;" ::: "memory")
#define CP_WAIT0()  asm volatile("cp.async.wait_group 0;" ::: "memory")

// fp16 k16-fragment interleave within a 64-wide k-stage
__device__ __forceinline__ int kpos64(int kk) {          // kk in [0,64)
    int g = kk >> 4, j = kk & 15;
    int lr = (j >> 1) & 3;
    int idx = ((j >> 3) << 1) | (j & 1);
    return (g >> 1) * 32 + lr * 8 + (g & 1) * 4 + idx;
}
__device__ __forceinline__ size_t ileave16(int m, int k) {   // offset in halves
    return ((size_t)((m >> 7) * NSTH + (k >> 6)) * 128 + (m & 127)) * 64
           + kpos64(k & 63);
}
__device__ __forceinline__ int swz8(int r) {
    return (((r & 1) << 2) | ((r >> 1) & 3));
}

// ---------------------------------------------------------------------------
// pre0_kernel (launch 0): chunk_sum (256) + Wc=W2@W_out (128) + summ_proj (32)
// 416 blocks x 512 threads. All branches dependency-free on other launches.
// ---------------------------------------------------------------------------
__global__ __launch_bounds__(512)
void pre0_kernel(const float* __restrict__ dec,
                 const float* __restrict__ summ, const float* __restrict__ W1,
                 const float* __restrict__ W2, const float* __restrict__ W_out) {
    __shared__ float sh[6400];             // 25 KB (Wc: As 64x68 + Bs 64x32)
    int blk = blockIdx.x;
    int tid = threadIdx.x;

    if (blk < 256) {                       // ---- chunk sums ----
        int b = blk / NCHUNK, c = blk % NCHUNK;
        const float* p = dec + ((size_t)(b * T_ + c * CHUNK)) * D_ + tid;
        float s = 0.f;
        #pragma unroll 8
        for (int t = 0; t < CHUNK; ++t) s += p[(size_t)t * D_];
        g_partial[(size_t)blk * D_ + tid] = s;
    } else if (blk < 384) {                // ---- Wc = W2 @ W_out (64x32 tile) ----
        int widx = blk - 256;              // 0..127
        int i0 = (widx & 7) * 64;          // rows of Wc (k of gemm2 B operand)
        int j0 = (widx >> 3) * 32;         // cols of Wc (n), 16 j-tiles
        float* As = sh;                    // [64][68] (272B rows, 16B-aligned)
        float* Bs = sh + 64 * 68;          // [64][32]
        int r = tid >> 3;                  // 0..63
        int c8 = (tid & 7) * 8;
        int bc4 = (tid & 7) * 4;
        int ti = tid >> 3;                 // output row 0..63
        int tjg = tid & 7;                 // output col group (4 cols)
        float a4[4];
        #pragma unroll
        for (int j = 0; j < 4; ++j) a4[j] = 0.f;

        for (int k0 = 0; k0 < 512; k0 += 64) {
            __syncthreads();
            *(float4*)&As[r * 68 + c8]     = *(const float4*)&W2[(size_t)(i0 + r) * D_ + k0 + c8];
            *(float4*)&As[r * 68 + c8 + 4] = *(const float4*)&W2[(size_t)(i0 + r) * D_ + k0 + c8 + 4];
            if (bc4 < 32)
                *(float4*)&Bs[r * 32 + bc4] = *(const float4*)&W_out[(size_t)(k0 + r) * D_ + j0 + bc4];
            __syncthreads();
            #pragma unroll 8
            for (int kk = 0; kk < 64; ++kk) {
                float a = As[ti * 68 + kk];
                float4 b0 = *(const float4*)&Bs[kk * 32 + tjg * 4];
                a4[0] = fmaf(a, b0.x, a4[0]); a4[1] = fmaf(a, b0.y, a4[1]);
                a4[2] = fmaf(a, b0.z, a4[2]); a4[3] = fmaf(a, b0.w, a4[3]);
            }
        }
        // store transposed+interleaved: Bt(n=j, k=i) = Wc[i][j]
        __half* Wc = g_hWt + (size_t)D_ * D_;
        int ii = i0 + ti;
        int kp = kpos64(ii & 63);
        int khi = ii >> 6;
        #pragma unroll
        for (int j = 0; j < 4; ++j) {
            int jj = j0 + tjg * 4 + j;
            size_t off = ((size_t)((jj >> 7) * NSTH + khi)) * 8192
                         + (size_t)(jj & 127) * 64 + kp;
            Wc[off] = __float2half_rn(a4[j]);
        }
    } else {                               // ---- summ_proj (fp32) ----
        int sidx = blk - 384;
        int b = sidx >> 2;
        int n0 = (sidx & 3) * 128;
        float* s = sh;
        float* red = sh + 512;
        int nl = tid & 127;
        int kg = tid >> 7;
        for (int i = tid; i < D_; i += 512) s[i] = summ[b * D_ + i];
        __syncthreads();
        float acc = 0.f;
        int k0 = kg * 128;
        #pragma unroll 8
        for (int k = 0; k < 128; ++k)
            acc = fmaf(s[k0 + k], W1[(size_t)(k0 + k) * D_ + n0 + nl], acc);
        red[kg * 128 + nl] = acc;
        __syncthreads();
        if (kg == 0)
            g_summ[b * D_ + n0 + nl] =
                red[nl] + red[128 + nl] + red[256 + nl] + red[384 + nl];
    }
}

// ---------------------------------------------------------------------------
// prep_kernel (launch 1): prefix (8) + W_hist transpose (256) + sp2 (32)
// ---------------------------------------------------------------------------
__global__ __launch_bounds__(512)
void prep_kernel(const float* __restrict__ W_hist,
                 const float* __restrict__ W_out, const float* __restrict__ b_out) {
    __shared__ float sh[1056];
    int blk = blockIdx.x;
    int tid = threadIdx.x;

    if (blk < 8) {                         // ---- chunk exclusive prefix ----
        int b = blk, d = tid;
        float run = 0.f;
        for (int c = 0; c < NCHUNK; ++c) {
            size_t idx = ((size_t)(b * NCHUNK + c)) * D_ + d;
            float v = g_partial[idx];
            g_partial[idx] = run;
            run += v;
        }
    } else if (blk < 264) {                // ---- W_hist transpose+interleave ----
        int r = blk - 8;
        int bx = (r & 15) * 32, by = (r >> 4) * 32;
        if (tid < 256) {
            int x = tid & 31, y = tid >> 5;
            float(*t)[33] = (float(*)[33])sh;
            #pragma unroll
            for (int i = 0; i < 32; i += 8)
                t[y + i][x] = W_hist[(size_t)(by + y + i) * D_ + bx + x];
            __syncthreads();
            #pragma unroll
            for (int i = 0; i < 32; i += 8)
                g_hWt[ileave16(bx + y + i, by + x)] = __float2half_rn(t[x][y + i]);
        } else {
            __syncthreads();
        }
    } else {                               // ---- sp2 = summ_proj@W_out + b_out ----
        int sidx = blk - 264;
        int b = sidx >> 2;
        int n0 = (sidx & 3) * 128;
        float* s = sh;
        float* red = sh + 512;
        int nl = tid & 127;
        int kg = tid >> 7;
        for (int i = tid; i < D_; i += 512) s[i] = g_summ[b * D_ + i];
        __syncthreads();
        float acc = 0.f;
        int k0 = kg * 128;
        #pragma unroll 8
        for (int k = 0; k < 128; ++k)
            acc = fmaf(s[k0 + k], W_out[(size_t)(k0 + k) * D_ + n0 + nl], acc);
        red[kg * 128 + nl] = acc;
        __syncthreads();
        if (kg == 0)
            g_summ2[b * D_ + n0 + nl] = b_out[n0 + nl] +
                red[nl] + red[128 + nl] + red[256 + nl] + red[384 + nl];
    }
}

// ---------------------------------------------------------------------------
// cum_mean (launch 2) -> g_hbufA (fp16, interleaved), 8x unrolled
// ---------------------------------------------------------------------------
__global__ void cum_mean_kernel(const float* __restrict__ dec) {
    int bc = blockIdx.x;
    int b = bc / NCHUNK, c = bc % NCHUNK;
    int d = threadIdx.x;
    size_t base = ((size_t)(b * T_ + c * CHUNK)) * D_ + d;
    float run = g_partial[(size_t)bc * D_ + d];
    size_t obase = ((size_t)((b * NCHUNK + c) * NSTH + (d >> 6)) * 128) * 64
                   + kpos64(d & 63);
    #pragma unroll 1
    for (int t = 0; t < CHUNK; t += 8) {
        float v[8];
        #pragma unroll
        for (int u = 0; u < 8; ++u)
            v[u] = dec[base + (size_t)(t + u) * D_];
        int tt = c * CHUNK + t;
        #pragma unroll
        for (int u = 0; u < 8; ++u) {
            run += v[u];
            g_hbufA[obase + (size_t)(t + u) * 64] =
                __float2half_rn(run / (float)(tt + u + 1));
        }
    }
}

// ---------------------------------------------------------------------------
// tc_gemm: mma.sync fp16 (m16n8k16), fully-unrolled 3-stage cp.async ring.
// Tile 128x128, BK=64, 8 warps, warp 32x64.
//   MODE 0: C(il,half) = half(tanh(acc + bias[col]))                (H)
//           -> packed 16B interleaved stores
//   MODE 2: C(fp32)    = tanh(vecb[b][col] - acc) + resid[row][col] (pre-LN x)
// ---------------------------------------------------------------------------
#define GM_THREADS 256
#define TILE_M 128
#define TILE_N 128
#define STG 16384                          // 128 rows x 128B

#define SM_A   0
#define SM_B   (3 * STG)                   // 49152
#define GEMM_SMEM (SM_B + 3 * STG)         // 98304 = 96KB -> 2 CTAs/SM

template <int MODE>
__global__ __launch_bounds__(GM_THREADS, 2)
void tc_gemm(const __half* __restrict__ A, const __half* __restrict__ Bt,
             const float* __restrict__ vec, const float* __restrict__ resid,
             void* __restrict__ Cv) {
    extern __shared__ char smem[];
    const uint32_t sbase = smem_u32(smem);

    const int tid = threadIdx.x;
    const int wid = tid >> 5, lane = tid & 31;
    const int row0 = blockIdx.y * TILE_M;
    const int col0 = blockIdx.x * TILE_N;
    const int wm = (wid & 3) * 32;
    const int wn = (wid >> 2) * 64;
    const int lq = lane >> 2;              // 0..7
    const int lr = lane & 3;               // 0..3

    const char* Ab = (const char*)A + (size_t)blockIdx.y * NSTH * 16384;
    const char* Bb = (const char*)Bt + (size_t)blockIdx.x * NSTH * 16384;
    const int frow = tid >> 3;             // 0..31
    const int fq = tid & 7;
    const uint32_t stchunk = (uint32_t)((fq ^ swz8(frow)) << 4);
    const uint32_t dA0 = sbase + SM_A + frow * 128 + stchunk;
    const uint32_t dB0 = sbase + SM_B + frow * 128 + stchunk;
    const size_t gsrc = (size_t)frow * 128 + fq * 16;

    const int swzl = swz8(lq);
    const int cc0 = (lr ^ swzl) << 4;
    const int cc1 = ((4 + lr) ^ swzl) << 4;

    const int aoff = (wm + lq) * 128;
    const int boff = (wn + lq) * 128;

    float acc[2][8][4];
    #pragma unroll
    for (int mt = 0; mt < 2; ++mt)
        #pragma unroll
        for (int nt = 0; nt < 8; ++nt)
            #pragma unroll
            for (int j = 0; j < 4; ++j) acc[mt][nt][j] = 0.f;

    #pragma unroll
    for (int p = 0; p < 2; ++p) {
        const char* as = Ab + (size_t)p * 16384;
        const char* bs = Bb + (size_t)p * 16384;
        #pragma unroll
        for (int i = 0; i < 4; ++i) {
            CP_ASYNC16(dA0 + p * STG + i * 4096, as + gsrc + (size_t)i * 4096);
            CP_ASYNC16(dB0 + p * STG + i * 4096, bs + gsrc + (size_t)i * 4096);
        }
        CP_COMMIT();
    }

    #pragma unroll
    for (int s = 0; s < NSTH; ++s) {
        const int buf = s % 3;
        if (s == NSTH - 1) { CP_WAIT0(); } else { CP_WAIT1(); }
        __syncthreads();
        if (s + 2 < NSTH) {
            const int bufn = (s + 2) % 3;
            const char* as = Ab + (size_t)(s + 2) * 16384;
            const char* bs = Bb + (size_t)(s + 2) * 16384;
            #pragma unroll
            for (int i = 0; i < 4; ++i) {
                CP_ASYNC16(dA0 + bufn * STG + i * 4096, as + gsrc + (size_t)i * 4096);
                CP_ASYNC16(dB0 + bufn * STG + i * 4096, bs + gsrc + (size_t)i * 4096);
            }
            CP_COMMIT();
        }

        const char* sa = smem + SM_A + buf * STG + aoff;
        const char* sb = smem + SM_B + buf * STG + boff;

        #pragma unroll
        for (int c = 0; c < 2; ++c) {
            const int co = c ? cc1 : cc0;
            uint4 qa0[2], qa1[2];
            #pragma unroll
            for (int mt = 0; mt < 2; ++mt) {
                qa0[mt] = *(const uint4*)(sa + mt * 2048 + co);
                qa1[mt] = *(const uint4*)(sa + mt * 2048 + 1024 + co);
            }
            uint32_t ag0[2][4], ag1[2][4];
            #pragma unroll
            for (int mt = 0; mt < 2; ++mt) {
                ag0[mt][0] = qa0[mt].x; ag0[mt][1] = qa1[mt].x;
                ag0[mt][2] = qa0[mt].y; ag0[mt][3] = qa1[mt].y;
                ag1[mt][0] = qa0[mt].z; ag1[mt][1] = qa1[mt].z;
                ag1[mt][2] = qa0[mt].w; ag1[mt][3] = qa1[mt].w;
            }
            uint4 pb = *(const uint4*)(sb + co);
            #pragma unroll
            for (int nt = 0; nt < 8; ++nt) {
                uint4 pc = pb;
                if (nt < 7)
                    pb = *(const uint4*)(sb + (nt + 1) * 1024 + co);
                uint32_t bg0[2] = { pc.x, pc.y };
                uint32_t bg1[2] = { pc.z, pc.w };
                mma_f16_16x8x16(acc[0][nt], ag0[0], bg0);
                mma_f16_16x8x16(acc[1][nt], ag0[1], bg0);
                mma_f16_16x8x16(acc[0][nt], ag1[0], bg1);
                mma_f16_16x8x16(acc[1][nt], ag1[1], bg1);
            }
        }
    }

    // ---------------- Epilogue ----------------
    const float* vbase = (MODE == 2) ? (vec + (size_t)(row0 / T_) * D_ + col0)
                                     : (vec + col0);
    if (MODE == 2) {
        float* C = (float*)Cv;
        #pragma unroll
        for (int mt = 0; mt < 2; ++mt) {
            int row = row0 + wm + mt * 16 + lq;
            #pragma unroll
            for (int nt = 0; nt < 8; ++nt) {
                int col = wn + nt * 8 + lr * 2;
                float b0 = vbase[col], b1 = vbase[col + 1];
                float c0 = acc[mt][nt][0], c1 = acc[mt][nt][1];
                float c2 = acc[mt][nt][2], c3 = acc[mt][nt][3];
                const float* r0p = resid + (size_t)row * D_ + col0 + col;
                const float* r1p = resid + (size_t)(row + 8) * D_ + col0 + col;
                float2 o0, o1;
                o0.x = tanhf(b0 - c0) + r0p[0];
                o0.y = tanhf(b1 - c1) + r0p[1];
                o1.x = tanhf(b0 - c2) + r1p[0];
                o1.y = tanhf(b1 - c3) + r1p[1];
                *(float2*)(C + (size_t)row * D_ + col0 + col) = o0;
                *(float2*)(C + (size_t)(row + 8) * D_ + col0 + col) = o1;
            }
        }
    } else {
        // Packed 16B interleaved stores: nt group of 4 (k+0,8,16,24 with same
        // lr) forms 8 consecutive halves at r*64 + pack*32 + lr*8.
        __half* Ch = (__half*)Cv;
        const size_t tilebase = (size_t)blockIdx.y * NSTH * 8192;   // halves
        #pragma unroll
        for (int mt = 0; mt < 2; ++mt) {
            int r = wm + mt * 16 + lq;
            #pragma unroll
            for (int pack = 0; pack < 2; ++pack) {
                int kabs = col0 + wn + pack * 32;        // k-block base
                size_t off = tilebase + (size_t)(kabs >> 6) * 8192
                             + (size_t)r * 64 + ((kabs & 63) >> 5) * 32 + lr * 8;
                __align__(16) __half2 h0[4];
                __align__(16) __half2 h1[4];             // rows r, r+8
                #pragma unroll
                for (int q = 0; q < 4; ++q) {
                    int nt = pack * 4 + q;
                    int col = wn + nt * 8 + lr * 2;
                    float b0 = vbase[col], b1 = vbase[col + 1];
                    h0[q] = __floats2half2_rn(tanhf(acc[mt][nt][0] + b0),
                                              tanhf(acc[mt][nt][1] + b1));
                    h1[q] = __floats2half2_rn(tanhf(acc[mt][nt][2] + b0),
                                              tanhf(acc[mt][nt][3] + b1));
                }
                *(uint4*)(Ch + off)       = *(const uint4*)h0;
                *(uint4*)(Ch + off + 512) = *(const uint4*)h1;   // row r+8
            }
        }
    }
}

// ---------------------------------------------------------------------------
// LayerNorm (last launch)
// ---------------------------------------------------------------------------
__global__ __launch_bounds__(256)
void layernorm_kernel(const float* __restrict__ X,
                      const float* __restrict__ gamma,
                      const float* __restrict__ beta,
                      float* __restrict__ out) {
    int row = blockIdx.x;
    const float* x = X + (size_t)row * D_;
    int tid = threadIdx.x;

    float v0 = x[tid];
    float v1 = x[tid + 256];
    float s = v0 + v1;
    float sq = v0 * v0 + v1 * v1;

    __shared__ float redS[8], redQ[8];
    #pragma unroll
    for (int o = 16; o > 0; o >>= 1) {
        s  += __shfl_down_sync(0xffffffffu, s, o);
        sq += __shfl_down_sync(0xffffffffu, sq, o);
    }
    if ((tid & 31) == 0) { redS[tid >> 5] = s; redQ[tid >> 5] = sq; }
    __syncthreads();
    if (tid < 32) {
        float a = (tid < 8) ? redS[tid] : 0.f;
        float b = (tid < 8) ? redQ[tid] : 0.f;
        #pragma unroll
        for (int o = 4; o > 0; o >>= 1) {
            a += __shfl_down_sync(0xffffffffu, a, o);
            b += __shfl_down_sync(0xffffffffu, b, o);
        }
        if (tid == 0) { redS[0] = a; redQ[0] = b; }
    }
    __syncthreads();

    float mu = redS[0] * (1.0f / D_);
    float var = redQ[0] * (1.0f / D_) - mu * mu;
    float rstd = rsqrtf(var + 1e-6f);

    float* o = out + (size_t)row * D_;
    o[tid]       = (v0 - mu) * rstd * gamma[tid] + beta[tid];
    o[tid + 256] = (v1 - mu) * rstd * gamma[tid + 256] + beta[tid + 256];
}

// ---------------------------------------------------------------------------
// Launcher — launch index 3 = gemm0 (the ncu-profiled slot)
// ---------------------------------------------------------------------------
extern "C" void kernel_launch(void* const* d_in, const int* in_sizes, int n_in,
                              void* d_out, int out_size) {
    const float* summ   = (const float*)d_in[0];
    const float* dec    = (const float*)d_in[1];
    const float* W_hist = (const float*)d_in[2];
    const float* b_hist = (const float*)d_in[3];
    const float* W1     = (const float*)d_in[4];
    const float* W2     = (const float*)d_in[5];
    const float* W_out  = (const float*)d_in[6];
    const float* b_out  = (const float*)d_in[7];
    const float* gamma  = (const float*)d_in[8];
    const float* beta   = (const float*)d_in[9];
    float* out = (float*)d_out;

    __half *hbufA, *hbufB, *hwt;
    float *fbuf, *summ2;
    cudaGetSymbolAddress((void**)&hbufA, g_hbufA);
    cudaGetSymbolAddress((void**)&hbufB, g_hbufB);
    cudaGetSymbolAddress((void**)&fbuf,  g_fbuf);
    cudaGetSymbolAddress((void**)&summ2, g_summ2);
    cudaGetSymbolAddress((void**)&hwt,   g_hWt);
    __half* WtHist = hwt;
    __half* Wc     = hwt + (size_t)D_ * D_;

    cudaFuncSetAttribute(tc_gemm<0>, cudaFuncAttributeMaxDynamicSharedMemorySize, GEMM_SMEM);
    cudaFuncSetAttribute(tc_gemm<2>, cudaFuncAttributeMaxDynamicSharedMemorySize, GEMM_SMEM);

    // 0: chunk sums + Wc=W2@W_out + summ_proj (all independent)
    pre0_kernel<<<416, 512>>>(dec, summ, W1, W2, W_out);
    // 1: prefix + W_hist transpose + sp2
    prep_kernel<<<296, 512>>>(W_hist, W_out, b_out);
    // 2: causal running mean -> hbufA (fp16, interleaved)
    cum_mean_kernel<<<B_ * NCHUNK, D_>>>(dec);

    dim3 ggrid(D_ / TILE_N, M_TOTAL / TILE_M);   // (4, 256)
    // 3: H = tanh(cum @ W_hist + b_hist)
    tc_gemm<0><<<ggrid, GM_THREADS, GEMM_SMEM>>>(hbufA, WtHist, b_hist, nullptr, hbufB);
    // 4: x = tanh(sp2[b] - H @ Wc) + dec
    tc_gemm<2><<<ggrid, GM_THREADS, GEMM_SMEM>>>(hbufB, Wc, summ2, dec, fbuf);

    // 5: LayerNorm
    layernorm_kernel<<<M_TOTAL, 256>>>(fbuf, gamma, beta, out);
}

// round 15
// speedup vs baseline: 1.4109x; 1.0467x over previous
#include <cuda_runtime.h>
#include <cuda_fp16.h>
#include <math.h>
#include <stdint.h>

// ---------------------------------------------------------------------------
// Problem constants
// ---------------------------------------------------------------------------
#define B_ 8
#define T_ 4096
#define D_ 512
#define M_TOTAL (B_ * T_)          // 32768
#define CHUNK 128
#define NCHUNK (T_ / CHUNK)        // 32
#define NSTH 8                     // k-stages (BK=64, fp16)

// ---------------------------------------------------------------------------
// Scratch
// ---------------------------------------------------------------------------
__device__ __half  g_hbufA[(size_t)M_TOTAL * D_];  // cum-mean -> later packed x
__device__ __half  g_hbufB[(size_t)M_TOTAL * D_];  // H, fp16 interleaved
__device__ float   g_partial[B_ * NCHUNK * D_];
__device__ float   g_summ[B_ * D_];                // summ_proj
__device__ float   g_summ2[B_ * D_];               // summ_proj@W_out + b_out
__device__ float2  g_stats[(size_t)M_TOTAL * 8];   // per-(row, tile, n-half) sum/sq
__device__ __half  g_hWt[2 * (size_t)D_ * D_];     // [0]=W_hist^T il, [1]=Wc^T il

// ---------------------------------------------------------------------------
// Helpers
// ---------------------------------------------------------------------------
__device__ __forceinline__ uint32_t smem_u32(const void* p) {
    uint32_t a;
    asm("{ .reg .u64 t; cvta.to.shared.u64 t, %1; cvt.u32.u64 %0, t; }"
        : "=r"(a) : "l"(p));
    return a;
}
__device__ __forceinline__ void mma_f16_16x8x16(float* d, const uint32_t* a,
                                                const uint32_t* b) {
    asm volatile(
        "mma.sync.aligned.m16n8k16.row.col.f32.f16.f16.f32 "
        "{%0,%1,%2,%3}, {%4,%5,%6,%7}, {%8,%9}, {%0,%1,%2,%3};"
        : "+f"(d[0]), "+f"(d[1]), "+f"(d[2]), "+f"(d[3])
        : "r"(a[0]), "r"(a[1]), "r"(a[2]), "r"(a[3]),
          "r"(b[0]), "r"(b[1]));
}

#define CP_ASYNC16(dst, src) \
    asm volatile("cp.async.cg.shared.global [%0], [%1], 16;" \
                 :: "r"(dst), "l"(src) : "memory")
#define CP_COMMIT() asm volatile("cp.async.commit_group;" ::: "memory")
#define CP_WAIT1()  asm volatile("cp.async.wait_group 1;" ::: "memory")
#define CP_WAIT0()  asm volatile("cp.async.wait_group 0;" ::: "memory")

// fp16 k16-fragment interleave within a 64-wide k-stage
__device__ __forceinline__ int kpos64(int kk) {          // kk in [0,64)
    int g = kk >> 4, j = kk & 15;
    int lr = (j >> 1) & 3;
    int idx = ((j >> 3) << 1) | (j & 1);
    return (g >> 1) * 32 + lr * 8 + (g & 1) * 4 + idx;
}
__device__ __forceinline__ size_t ileave16(int m, int k) {   // offset in halves
    return ((size_t)((m >> 7) * NSTH + (k >> 6)) * 128 + (m & 127)) * 64
           + kpos64(k & 63);
}
__device__ __forceinline__ int swz8(int r) {
    return (((r & 1) << 2) | ((r >> 1) & 3));
}

// ---------------------------------------------------------------------------
// pre0_kernel (launch 0): chunk_sum (256) + Wc=W2@W_out (128) + summ_proj (32)
// ---------------------------------------------------------------------------
__global__ __launch_bounds__(512)
void pre0_kernel(const float* __restrict__ dec,
                 const float* __restrict__ summ, const float* __restrict__ W1,
                 const float* __restrict__ W2, const float* __restrict__ W_out) {
    __shared__ float sh[6400];             // 25 KB (Wc: As 64x68 + Bs 64x32)
    int blk = blockIdx.x;
    int tid = threadIdx.x;

    if (blk < 256) {                       // ---- chunk sums ----
        int b = blk / NCHUNK, c = blk % NCHUNK;
        const float* p = dec + ((size_t)(b * T_ + c * CHUNK)) * D_ + tid;
        float s = 0.f;
        #pragma unroll 8
        for (int t = 0; t < CHUNK; ++t) s += p[(size_t)t * D_];
        g_partial[(size_t)blk * D_ + tid] = s;
    } else if (blk < 384) {                // ---- Wc = W2 @ W_out (64x32 tile) ----
        int widx = blk - 256;              // 0..127
        int i0 = (widx & 7) * 64;
        int j0 = (widx >> 3) * 32;
        float* As = sh;                    // [64][68]
        float* Bs = sh + 64 * 68;          // [64][32]
        int r = tid >> 3;
        int c8 = (tid & 7) * 8;
        int bc4 = (tid & 7) * 4;
        int ti = tid >> 3;
        int tjg = tid & 7;
        float a4[4];
        #pragma unroll
        for (int j = 0; j < 4; ++j) a4[j] = 0.f;

        for (int k0 = 0; k0 < 512; k0 += 64) {
            __syncthreads();
            *(float4*)&As[r * 68 + c8]     = *(const float4*)&W2[(size_t)(i0 + r) * D_ + k0 + c8];
            *(float4*)&As[r * 68 + c8 + 4] = *(const float4*)&W2[(size_t)(i0 + r) * D_ + k0 + c8 + 4];
            if (bc4 < 32)
                *(float4*)&Bs[r * 32 + bc4] = *(const float4*)&W_out[(size_t)(k0 + r) * D_ + j0 + bc4];
            __syncthreads();
            #pragma unroll 8
            for (int kk = 0; kk < 64; ++kk) {
                float a = As[ti * 68 + kk];
                float4 b0 = *(const float4*)&Bs[kk * 32 + tjg * 4];
                a4[0] = fmaf(a, b0.x, a4[0]); a4[1] = fmaf(a, b0.y, a4[1]);
                a4[2] = fmaf(a, b0.z, a4[2]); a4[3] = fmaf(a, b0.w, a4[3]);
            }
        }
        __half* Wc = g_hWt + (size_t)D_ * D_;
        int ii = i0 + ti;
        int kp = kpos64(ii & 63);
        int khi = ii >> 6;
        #pragma unroll
        for (int j = 0; j < 4; ++j) {
            int jj = j0 + tjg * 4 + j;
            size_t off = ((size_t)((jj >> 7) * NSTH + khi)) * 8192
                         + (size_t)(jj & 127) * 64 + kp;
            Wc[off] = __float2half_rn(a4[j]);
        }
    } else {                               // ---- summ_proj (fp32) ----
        int sidx = blk - 384;
        int b = sidx >> 2;
        int n0 = (sidx & 3) * 128;
        float* s = sh;
        float* red = sh + 512;
        int nl = tid & 127;
        int kg = tid >> 7;
        for (int i = tid; i < D_; i += 512) s[i] = summ[b * D_ + i];
        __syncthreads();
        float acc = 0.f;
        int k0 = kg * 128;
        #pragma unroll 8
        for (int k = 0; k < 128; ++k)
            acc = fmaf(s[k0 + k], W1[(size_t)(k0 + k) * D_ + n0 + nl], acc);
        red[kg * 128 + nl] = acc;
        __syncthreads();
        if (kg == 0)
            g_summ[b * D_ + n0 + nl] =
                red[nl] + red[128 + nl] + red[256 + nl] + red[384 + nl];
    }
}

// ---------------------------------------------------------------------------
// prep_kernel (launch 1): prefix (8) + W_hist transpose (256) + sp2 (32)
// ---------------------------------------------------------------------------
__global__ __launch_bounds__(512)
void prep_kernel(const float* __restrict__ W_hist,
                 const float* __restrict__ W_out, const float* __restrict__ b_out) {
    __shared__ float sh[1056];
    int blk = blockIdx.x;
    int tid = threadIdx.x;

    if (blk < 8) {
        int b = blk, d = tid;
        float run = 0.f;
        for (int c = 0; c < NCHUNK; ++c) {
            size_t idx = ((size_t)(b * NCHUNK + c)) * D_ + d;
            float v = g_partial[idx];
            g_partial[idx] = run;
            run += v;
        }
    } else if (blk < 264) {
        int r = blk - 8;
        int bx = (r & 15) * 32, by = (r >> 4) * 32;
        if (tid < 256) {
            int x = tid & 31, y = tid >> 5;
            float(*t)[33] = (float(*)[33])sh;
            #pragma unroll
            for (int i = 0; i < 32; i += 8)
                t[y + i][x] = W_hist[(size_t)(by + y + i) * D_ + bx + x];
            __syncthreads();
            #pragma unroll
            for (int i = 0; i < 32; i += 8)
                g_hWt[ileave16(bx + y + i, by + x)] = __float2half_rn(t[x][y + i]);
        } else {
            __syncthreads();
        }
    } else {
        int sidx = blk - 264;
        int b = sidx >> 2;
        int n0 = (sidx & 3) * 128;
        float* s = sh;
        float* red = sh + 512;
        int nl = tid & 127;
        int kg = tid >> 7;
        for (int i = tid; i < D_; i += 512) s[i] = g_summ[b * D_ + i];
        __syncthreads();
        float acc = 0.f;
        int k0 = kg * 128;
        #pragma unroll 8
        for (int k = 0; k < 128; ++k)
            acc = fmaf(s[k0 + k], W_out[(size_t)(k0 + k) * D_ + n0 + nl], acc);
        red[kg * 128 + nl] = acc;
        __syncthreads();
        if (kg == 0)
            g_summ2[b * D_ + n0 + nl] = b_out[n0 + nl] +
                red[nl] + red[128 + nl] + red[256 + nl] + red[384 + nl];
    }
}

// ---------------------------------------------------------------------------
// cum_mean (launch 2) -> g_hbufA (fp16, interleaved), 8x unrolled
// ---------------------------------------------------------------------------
__global__ void cum_mean_kernel(const float* __restrict__ dec) {
    int bc = blockIdx.x;
    int b = bc / NCHUNK, c = bc % NCHUNK;
    int d = threadIdx.x;
    size_t base = ((size_t)(b * T_ + c * CHUNK)) * D_ + d;
    float run = g_partial[(size_t)bc * D_ + d];
    size_t obase = ((size_t)((b * NCHUNK + c) * NSTH + (d >> 6)) * 128) * 64
                   + kpos64(d & 63);
    #pragma unroll 1
    for (int t = 0; t < CHUNK; t += 8) {
        float v[8];
        #pragma unroll
        for (int u = 0; u < 8; ++u)
            v[u] = dec[base + (size_t)(t + u) * D_];
        int tt = c * CHUNK + t;
        #pragma unroll
        for (int u = 0; u < 8; ++u) {
            run += v[u];
            g_hbufA[obase + (size_t)(t + u) * 64] =
                __float2half_rn(run / (float)(tt + u + 1));
        }
    }
}

// ---------------------------------------------------------------------------
// tc_gemm: mma.sync fp16 (m16n8k16), fully-unrolled 3-stage cp.async ring.
// Tile 128x128, BK=64, 8 warps, warp 32x64.
//   MODE 0: C(il,half) = half(tanh(acc + bias[col]))          packed 16B stores
//   MODE 2: C(il,half) = half(tanh(vecb[b][col]-acc)+resid)   packed 16B stores
//           + per-(row,tile,n-half) partial LN stats -> g_stats
// ---------------------------------------------------------------------------
#define GM_THREADS 256
#define TILE_M 128
#define TILE_N 128
#define STG 16384                          // 128 rows x 128B

#define SM_A   0
#define SM_B   (3 * STG)                   // 49152
#define GEMM_SMEM (SM_B + 3 * STG)         // 98304 = 96KB -> 2 CTAs/SM

template <int MODE>
__global__ __launch_bounds__(GM_THREADS, 2)
void tc_gemm(const __half* __restrict__ A, const __half* __restrict__ Bt,
             const float* __restrict__ vec, const float* __restrict__ resid,
             __half* __restrict__ Cv) {
    extern __shared__ char smem[];
    const uint32_t sbase = smem_u32(smem);

    const int tid = threadIdx.x;
    const int wid = tid >> 5, lane = tid & 31;
    const int row0 = blockIdx.y * TILE_M;
    const int col0 = blockIdx.x * TILE_N;
    const int wm = (wid & 3) * 32;
    const int wn = (wid >> 2) * 64;
    const int lq = lane >> 2;              // 0..7
    const int lr = lane & 3;               // 0..3

    const char* Ab = (const char*)A + (size_t)blockIdx.y * NSTH * 16384;
    const char* Bb = (const char*)Bt + (size_t)blockIdx.x * NSTH * 16384;
    const int frow = tid >> 3;             // 0..31
    const int fq = tid & 7;
    const uint32_t stchunk = (uint32_t)((fq ^ swz8(frow)) << 4);
    const uint32_t dA0 = sbase + SM_A + frow * 128 + stchunk;
    const uint32_t dB0 = sbase + SM_B + frow * 128 + stchunk;
    const size_t gsrc = (size_t)frow * 128 + fq * 16;

    const int swzl = swz8(lq);
    const int cc0 = (lr ^ swzl) << 4;
    const int cc1 = ((4 + lr) ^ swzl) << 4;

    const int aoff = (wm + lq) * 128;
    const int boff = (wn + lq) * 128;

    float acc[2][8][4];
    #pragma unroll
    for (int mt = 0; mt < 2; ++mt)
        #pragma unroll
        for (int nt = 0; nt < 8; ++nt)
            #pragma unroll
            for (int j = 0; j < 4; ++j) acc[mt][nt][j] = 0.f;

    #pragma unroll
    for (int p = 0; p < 2; ++p) {
        const char* as = Ab + (size_t)p * 16384;
        const char* bs = Bb + (size_t)p * 16384;
        #pragma unroll
        for (int i = 0; i < 4; ++i) {
            CP_ASYNC16(dA0 + p * STG + i * 4096, as + gsrc + (size_t)i * 4096);
            CP_ASYNC16(dB0 + p * STG + i * 4096, bs + gsrc + (size_t)i * 4096);
        }
        CP_COMMIT();
    }

    #pragma unroll
    for (int s = 0; s < NSTH; ++s) {
        const int buf = s % 3;
        if (s == NSTH - 1) { CP_WAIT0(); } else { CP_WAIT1(); }
        __syncthreads();
        if (s + 2 < NSTH) {
            const int bufn = (s + 2) % 3;
            const char* as = Ab + (size_t)(s + 2) * 16384;
            const char* bs = Bb + (size_t)(s + 2) * 16384;
            #pragma unroll
            for (int i = 0; i < 4; ++i) {
                CP_ASYNC16(dA0 + bufn * STG + i * 4096, as + gsrc + (size_t)i * 4096);
                CP_ASYNC16(dB0 + bufn * STG + i * 4096, bs + gsrc + (size_t)i * 4096);
            }
            CP_COMMIT();
        }

        const char* sa = smem + SM_A + buf * STG + aoff;
        const char* sb = smem + SM_B + buf * STG + boff;

        #pragma unroll
        for (int c = 0; c < 2; ++c) {
            const int co = c ? cc1 : cc0;
            uint4 qa0[2], qa1[2];
            #pragma unroll
            for (int mt = 0; mt < 2; ++mt) {
                qa0[mt] = *(const uint4*)(sa + mt * 2048 + co);
                qa1[mt] = *(const uint4*)(sa + mt * 2048 + 1024 + co);
            }
            uint32_t ag0[2][4], ag1[2][4];
            #pragma unroll
            for (int mt = 0; mt < 2; ++mt) {
                ag0[mt][0] = qa0[mt].x; ag0[mt][1] = qa1[mt].x;
                ag0[mt][2] = qa0[mt].y; ag0[mt][3] = qa1[mt].y;
                ag1[mt][0] = qa0[mt].z; ag1[mt][1] = qa1[mt].z;
                ag1[mt][2] = qa0[mt].w; ag1[mt][3] = qa1[mt].w;
            }
            uint4 pb = *(const uint4*)(sb + co);
            #pragma unroll
            for (int nt = 0; nt < 8; ++nt) {
                uint4 pc = pb;
                if (nt < 7)
                    pb = *(const uint4*)(sb + (nt + 1) * 1024 + co);
                uint32_t bg0[2] = { pc.x, pc.y };
                uint32_t bg1[2] = { pc.z, pc.w };
                mma_f16_16x8x16(acc[0][nt], ag0[0], bg0);
                mma_f16_16x8x16(acc[1][nt], ag0[1], bg0);
                mma_f16_16x8x16(acc[0][nt], ag1[0], bg1);
                mma_f16_16x8x16(acc[1][nt], ag1[1], bg1);
            }
        }
    }

    // ---------------- Epilogue: packed 16B interleaved stores ----------------
    const float* vbase = (MODE == 2) ? (vec + (size_t)(row0 / T_) * D_ + col0)
                                     : (vec + col0);
    const size_t tilebase = (size_t)blockIdx.y * NSTH * 8192;   // halves
    const int wnidx = wid >> 2;

    #pragma unroll
    for (int mt = 0; mt < 2; ++mt) {
        int r = wm + mt * 16 + lq;
        float s0 = 0.f, q0 = 0.f, s1 = 0.f, q1 = 0.f;
        #pragma unroll
        for (int pack = 0; pack < 2; ++pack) {
            int kabs = col0 + wn + pack * 32;
            size_t off = tilebase + (size_t)(kabs >> 6) * 8192
                         + (size_t)r * 64 + ((kabs & 63) >> 5) * 32 + lr * 8;
            __align__(16) __half2 h0[4];
            __align__(16) __half2 h1[4];
            #pragma unroll
            for (int q = 0; q < 4; ++q) {
                int nt = pack * 4 + q;
                int col = wn + nt * 8 + lr * 2;
                float b0 = vbase[col], b1 = vbase[col + 1];
                if (MODE == 0) {
                    h0[q] = __floats2half2_rn(tanhf(acc[mt][nt][0] + b0),
                                              tanhf(acc[mt][nt][1] + b1));
                    h1[q] = __floats2half2_rn(tanhf(acc[mt][nt][2] + b0),
                                              tanhf(acc[mt][nt][3] + b1));
                } else {
                    int row = row0 + r;
                    float2 rd0 = *(const float2*)(resid + (size_t)row * D_ + col0 + col);
                    float2 rd1 = *(const float2*)(resid + (size_t)(row + 8) * D_ + col0 + col);
                    float x0 = tanhf(b0 - acc[mt][nt][0]) + rd0.x;
                    float x1 = tanhf(b1 - acc[mt][nt][1]) + rd0.y;
                    float x2 = tanhf(b0 - acc[mt][nt][2]) + rd1.x;
                    float x3 = tanhf(b1 - acc[mt][nt][3]) + rd1.y;
                    s0 += x0 + x1; q0 += x0 * x0 + x1 * x1;
                    s1 += x2 + x3; q1 += x2 * x2 + x3 * x3;
                    h0[q] = __floats2half2_rn(x0, x1);
                    h1[q] = __floats2half2_rn(x2, x3);
                }
            }
            *(uint4*)(Cv + off)       = *(const uint4*)h0;
            *(uint4*)(Cv + off + 512) = *(const uint4*)h1;     // row r+8
        }
        if (MODE == 2) {
            // reduce across lr lanes (bits 0-1 of lane id)
            #pragma unroll
            for (int o = 1; o <= 2; o <<= 1) {
                s0 += __shfl_xor_sync(0xffffffffu, s0, o);
                q0 += __shfl_xor_sync(0xffffffffu, q0, o);
                s1 += __shfl_xor_sync(0xffffffffu, s1, o);
                q1 += __shfl_xor_sync(0xffffffffu, q1, o);
            }
            if (lr == 0) {
                int row = row0 + r;
                g_stats[((size_t)row * 4 + blockIdx.x) * 2 + wnidx] =
                    make_float2(s0, q0);
                g_stats[((size_t)(row + 8) * 4 + blockIdx.x) * 2 + wnidx] =
                    make_float2(s1, q1);
            }
        }
    }
}

// ---------------------------------------------------------------------------
// LayerNorm normalize pass: stats precomputed; packed fp16 x -> fp32 out
// ---------------------------------------------------------------------------
__global__ __launch_bounds__(256)
void layernorm_kernel(const __half* __restrict__ X,
                      const float* __restrict__ gamma,
                      const float* __restrict__ beta,
                      float* __restrict__ out) {
    int row = blockIdx.x;
    int tid = threadIdx.x;

    float sum = 0.f, sq = 0.f;
    #pragma unroll
    for (int i = 0; i < 8; ++i) {
        float2 st = g_stats[(size_t)row * 8 + i];
        sum += st.x; sq += st.y;
    }
    float mu = sum * (1.0f / D_);
    float var = sq * (1.0f / D_) - mu * mu;
    float rstd = rsqrtf(var + 1e-6f);

    // thread handles packed positions p = 2*tid, 2*tid+1
    int p = tid * 2;
    int kb = p >> 6;
    int within = p & 63;
    int chunk = within >> 5;
    int p32 = within & 31;
    int lr = p32 >> 3;
    int q = (p32 >> 1) & 3;
    size_t addr = ((size_t)(row >> 7) * NSTH + kb) * 8192
                  + (size_t)(row & 127) * 64 + chunk * 32 + p32;
    __half2 hv = *(const __half2*)(X + addr);
    int col = kb * 64 + chunk * 32 + q * 8 + lr * 2;
    float2 g = *(const float2*)(gamma + col);
    float2 be = *(const float2*)(beta + col);
    float2 o;
    o.x = (__low2float(hv)  - mu) * rstd * g.x + be.x;
    o.y = (__high2float(hv) - mu) * rstd * g.y + be.y;
    *(float2*)(out + (size_t)row * D_ + col) = o;
}

// ---------------------------------------------------------------------------
// Launcher — launch index 3 = gemm0 (the ncu-profiled slot)
// ---------------------------------------------------------------------------
extern "C" void kernel_launch(void* const* d_in, const int* in_sizes, int n_in,
                              void* d_out, int out_size) {
    const float* summ   = (const float*)d_in[0];
    const float* dec    = (const float*)d_in[1];
    const float* W_hist = (const float*)d_in[2];
    const float* b_hist = (const float*)d_in[3];
    const float* W1     = (const float*)d_in[4];
    const float* W2     = (const float*)d_in[5];
    const float* W_out  = (const float*)d_in[6];
    const float* b_out  = (const float*)d_in[7];
    const float* gamma  = (const float*)d_in[8];
    const float* beta   = (const float*)d_in[9];
    float* out = (float*)d_out;

    __half *hbufA, *hbufB, *hwt;
    float *summ2;
    cudaGetSymbolAddress((void**)&hbufA, g_hbufA);
    cudaGetSymbolAddress((void**)&hbufB, g_hbufB);
    cudaGetSymbolAddress((void**)&summ2, g_summ2);
    cudaGetSymbolAddress((void**)&hwt,   g_hWt);
    __half* WtHist = hwt;
    __half* Wc     = hwt + (size_t)D_ * D_;

    cudaFuncSetAttribute(tc_gemm<0>, cudaFuncAttributeMaxDynamicSharedMemorySize, GEMM_SMEM);
    cudaFuncSetAttribute(tc_gemm<2>, cudaFuncAttributeMaxDynamicSharedMemorySize, GEMM_SMEM);

    // 0: chunk sums + Wc=W2@W_out + summ_proj (all independent)
    pre0_kernel<<<416, 512>>>(dec, summ, W1, W2, W_out);
    // 1: prefix + W_hist transpose + sp2
    prep_kernel<<<296, 512>>>(W_hist, W_out, b_out);
    // 2: causal running mean -> hbufA (fp16, interleaved)
    cum_mean_kernel<<<B_ * NCHUNK, D_>>>(dec);

    dim3 ggrid(D_ / TILE_N, M_TOTAL / TILE_M);   // (4, 256)
    // 3: H = tanh(cum @ W_hist + b_hist)
    tc_gemm<0><<<ggrid, GM_THREADS, GEMM_SMEM>>>(hbufA, WtHist, b_hist, nullptr, hbufB);
    // 4: x = tanh(sp2[b] - H @ Wc) + dec  (packed fp16 into hbufA) + LN stats
    tc_gemm<2><<<ggrid, GM_THREADS, GEMM_SMEM>>>(hbufB, Wc, summ2, dec, hbufA);

    // 5: LayerNorm normalize pass
    layernorm_kernel<<<M_TOTAL, 256>>>(hbufA, gamma, beta, out);
}